// round 4
// baseline (speedup 1.0000x reference)
#include <cuda_runtime.h>
#include <math.h>

#define Bc 4
#define Tc 2048
#define Ec 1024
#define Hc 16
#define Dc 64
#define Fc 32
#define Mc (Bc*Tc)   // 8192

// Scratch (allocation-free contract: __device__ globals)
__device__ float g_Q[Bc*Hc*Tc*Dc];   // (B,H,T,D)
__device__ float g_K[Bc*Hc*Tc*Dc];
__device__ float g_V[Bc*Hc*Tc*Dc];
__device__ float g_O[Bc*Tc*Ec];      // (B,T,E) attention output

// ---------------------------------------------------------------------------
// GEMM: C[M,N] = A[M,K] @ W[N,K]^T + bias[N]
// MODE 0: plain A arg -> plain store to C.
// MODE 1: plain A arg -> scatter into g_Q/g_K/g_V (B,H,T,D).
// MODE 2: A taken from g_O (device-side symbol; NEVER pass __device__ globals
//         as kernel args from host — host sees the shadow symbol, and with
//         GB300 ATS that silently reads host zeros instead of trapping).
// Tiling: 128x128x16, 256 threads, 8x8 accum per thread.
// ---------------------------------------------------------------------------
template<int MODE>
__global__ __launch_bounds__(256) void gemm_kernel(
    const float* __restrict__ A_arg, const float* __restrict__ W,
    const float* __restrict__ bias, float* __restrict__ C,
    int M, int N, int K)
{
    const float* __restrict__ A = (MODE == 2) ? (const float*)g_O : A_arg;

    __shared__ float As[16][128];
    __shared__ float Ws[16][128];

    const int tid = threadIdx.x;
    const int tx = tid & 15;          // 0..15 -> N direction
    const int ty = tid >> 4;          // 0..15 -> M direction
    const int bm = blockIdx.y * 128;
    const int bn = blockIdx.x * 128;

    float acc[8][8];
    #pragma unroll
    for (int i = 0; i < 8; i++)
        #pragma unroll
        for (int j = 0; j < 8; j++) acc[i][j] = 0.f;

    for (int kb = 0; kb < K; kb += 16) {
        // cooperative load of A and W 128x16 tiles (transposed into smem)
        #pragma unroll
        for (int l = 0; l < 2; l++) {
            int v   = l * 256 + tid;        // 0..511
            int row = v >> 2;               // 0..127
            int seg = v & 3;                // 0..3 (float4 within 16-wide K slice)
            float4 a4 = *(const float4*)&A[(size_t)(bm + row) * K + kb + seg * 4];
            As[seg*4+0][row] = a4.x; As[seg*4+1][row] = a4.y;
            As[seg*4+2][row] = a4.z; As[seg*4+3][row] = a4.w;
            float4 w4 = *(const float4*)&W[(size_t)(bn + row) * K + kb + seg * 4];
            Ws[seg*4+0][row] = w4.x; Ws[seg*4+1][row] = w4.y;
            Ws[seg*4+2][row] = w4.z; Ws[seg*4+3][row] = w4.w;
        }
        __syncthreads();

        #pragma unroll
        for (int kk = 0; kk < 16; kk++) {
            float a[8], b[8];
            *(float4*)&a[0] = *(const float4*)&As[kk][ty*8];
            *(float4*)&a[4] = *(const float4*)&As[kk][ty*8+4];
            *(float4*)&b[0] = *(const float4*)&Ws[kk][tx*8];
            *(float4*)&b[4] = *(const float4*)&Ws[kk][tx*8+4];
            #pragma unroll
            for (int i = 0; i < 8; i++)
                #pragma unroll
                for (int j = 0; j < 8; j++)
                    acc[i][j] += a[i] * b[j];
        }
        __syncthreads();
    }

    // epilogue: hoist per-thread bias (8 columns) once
    float bv[8];
    #pragma unroll
    for (int j = 0; j < 8; j++) bv[j] = bias[bn + tx*8 + j];

    #pragma unroll
    for (int i = 0; i < 8; i++) {
        int m = bm + ty*8 + i;
        #pragma unroll
        for (int j = 0; j < 8; j++) {
            int n = bn + tx*8 + j;
            float val = acc[i][j] + bv[j];
            if (MODE != 1) {
                C[(size_t)m * N + n] = val;
            } else {
                int which = n >> 10;                 // 0=Q 1=K 2=V
                int nn = n & 1023;
                int hh = nn >> 6, dd = nn & 63;
                int bb = m >> 11, tt = m & 2047;
                float* dst = (which == 0) ? g_Q : (which == 1) ? g_K : g_V;
                dst[((size_t)(bb * Hc + hh) * Tc + tt) * Dc + dd] = val;
            }
        }
    }
}

// ---------------------------------------------------------------------------
// Rotary: one warp per (b,h,t), lane = pair index f.
// angle = positions[b,t,:] . freqs[h,f,:]; rotate (Q,K) pairs in place.
// ---------------------------------------------------------------------------
__global__ __launch_bounds__(256) void rotary_kernel(
    const float* __restrict__ pos, const float* __restrict__ freqs)
{
    int w = blockIdx.x * 8 + (threadIdx.x >> 5);     // global warp id
    int f = threadIdx.x & 31;
    int b = w / (Hc * Tc);
    int rem = w - b * (Hc * Tc);
    int h = rem / Tc;
    int t = rem - h * Tc;

    float px = pos[(size_t)(b * Tc + t) * 3 + 0];
    float py = pos[(size_t)(b * Tc + t) * 3 + 1];
    float pz = pos[(size_t)(b * Tc + t) * 3 + 2];
    float fx = freqs[(size_t)(h * Fc + f) * 3 + 0];
    float fy = freqs[(size_t)(h * Fc + f) * 3 + 1];
    float fz = freqs[(size_t)(h * Fc + f) * 3 + 2];
    float ang = px * fx + py * fy + pz * fz;
    float s, c;
    __sincosf(ang, &s, &c);

    size_t base = ((size_t)(b * Hc + h) * Tc + t) * Dc + 2 * f;
    float q0 = g_Q[base], q1 = g_Q[base + 1];
    g_Q[base]     = q0 * c - q1 * s;
    g_Q[base + 1] = q0 * s + q1 * c;
    float k0 = g_K[base], k1 = g_K[base + 1];
    g_K[base]     = k0 * c - k1 * s;
    g_K[base + 1] = k0 * s + k1 * c;
}

// ---------------------------------------------------------------------------
// Flash attention (fp32): block = 128 query rows of one (b,h); thread = 1 row.
// KV tiles of 32 keys staged in smem (broadcast reads). Online softmax in
// base-2 domain: q pre-scaled by (1/sqrt(D)) * log2(e), so p = exp2f(s - m).
// Output written to g_O in (B,T,E) layout so out-proj GEMM reads it directly.
// ---------------------------------------------------------------------------
__global__ __launch_bounds__(128) void attn_kernel()
{
    __shared__ float Ks[32 * 64];
    __shared__ float Vs[32 * 64];

    const int tid = threadIdx.x;
    const int qt = blockIdx.x, h = blockIdx.y, b = blockIdx.z;
    const int bh = b * Hc + h;
    const float* Qb = g_Q + (size_t)bh * Tc * Dc;
    const float* Kb = g_K + (size_t)bh * Tc * Dc;
    const float* Vb = g_V + (size_t)bh * Tc * Dc;
    const int row = qt * 128 + tid;

    // load & pre-scale q row into registers: 0.125 (=1/sqrt(64)) * log2(e)
    const float qs = 0.125f * 1.4426950408889634f;
    float q[64];
    {
        const float4* qsrc = (const float4*)(Qb + (size_t)row * Dc);
        #pragma unroll
        for (int i = 0; i < 16; i++) {
            float4 v = qsrc[i];
            q[4*i+0] = v.x * qs; q[4*i+1] = v.y * qs;
            q[4*i+2] = v.z * qs; q[4*i+3] = v.w * qs;
        }
    }

    float o[64];
    #pragma unroll
    for (int k = 0; k < 64; k++) o[k] = 0.f;
    float mval = -1e30f, l = 0.f;

    for (int kt = 0; kt < Tc / 32; kt++) {
        // cooperative tile load: 32 keys x 64 dims (8 KB each for K and V)
        const float4* ksrc = (const float4*)(Kb + (size_t)kt * 32 * 64);
        const float4* vsrc = (const float4*)(Vb + (size_t)kt * 32 * 64);
        float4* kd = (float4*)Ks;
        float4* vd = (float4*)Vs;
        #pragma unroll
        for (int i = 0; i < 4; i++) {
            kd[tid + 128 * i] = ksrc[tid + 128 * i];
            vd[tid + 128 * i] = vsrc[tid + 128 * i];
        }
        __syncthreads();

        float s[32];
        float tm = mval;
        #pragma unroll
        for (int j = 0; j < 32; j++) {
            const float4* kr = (const float4*)(Ks + j * 64);
            float sj = 0.f;
            #pragma unroll
            for (int k4 = 0; k4 < 16; k4++) {
                float4 kv = kr[k4];
                sj += q[4*k4+0] * kv.x + q[4*k4+1] * kv.y
                    + q[4*k4+2] * kv.z + q[4*k4+3] * kv.w;
            }
            s[j] = sj;
            tm = fmaxf(tm, sj);
        }

        float corr = exp2f(mval - tm);   // base-2 online softmax
        mval = tm;
        l *= corr;
        #pragma unroll
        for (int k = 0; k < 64; k++) o[k] *= corr;

        #pragma unroll
        for (int j = 0; j < 32; j++) {
            float p = exp2f(s[j] - mval);
            l += p;
            const float4* vr = (const float4*)(Vs + j * 64);
            #pragma unroll
            for (int k4 = 0; k4 < 16; k4++) {
                float4 vv = vr[k4];
                o[4*k4+0] += p * vv.x; o[4*k4+1] += p * vv.y;
                o[4*k4+2] += p * vv.z; o[4*k4+3] += p * vv.w;
            }
        }
        __syncthreads();
    }

    float inv = 1.f / l;
    float* od = g_O + (size_t)(b * Tc + row) * Ec + h * Dc;
    #pragma unroll
    for (int k4 = 0; k4 < 16; k4++) {
        float4 v;
        v.x = o[4*k4+0] * inv; v.y = o[4*k4+1] * inv;
        v.z = o[4*k4+2] * inv; v.w = o[4*k4+3] * inv;
        ((float4*)od)[k4] = v;
    }
}

// ---------------------------------------------------------------------------
extern "C" void kernel_launch(void* const* d_in, const int* in_sizes, int n_in,
                              void* d_out, int out_size)
{
    const float* query = (const float*)d_in[0];   // (B,T,E)
    const float* pos   = (const float*)d_in[1];   // (B,T,3)
    const float* wqkv  = (const float*)d_in[2];   // (3E,E)
    const float* bqkv  = (const float*)d_in[3];   // (3E,)
    const float* wo    = (const float*)d_in[4];   // (E,E)
    const float* bo    = (const float*)d_in[5];   // (E,)
    const float* freqs = (const float*)d_in[6];   // (H,F,3)
    float* out = (float*)d_out;

    // 1) QKV projection, scattered to (B,H,T,D)
    {
        dim3 grid(3 * Ec / 128, Mc / 128);       // (24, 64)
        gemm_kernel<1><<<grid, 256>>>(query, wqkv, bqkv, nullptr, Mc, 3 * Ec, Ec);
    }
    // 2) rotary on Q and K
    {
        int warps = Bc * Hc * Tc;                // 131072
        rotary_kernel<<<warps / 8, 256>>>(pos, freqs);
    }
    // 3) attention
    {
        dim3 grid(Tc / 128, Hc, Bc);             // (16, 16, 4)
        attn_kernel<<<grid, 128>>>();
    }
    // 4) output projection: A = g_O read via device-side symbol (MODE 2)
    {
        dim3 grid(Ec / 128, Mc / 128);           // (8, 64)
        gemm_kernel<2><<<grid, 256>>>(nullptr, wo, bo, out, Mc, Ec, Ec);
    }
}

// round 14
// speedup vs baseline: 1.6473x; 1.6473x over previous
#include <cuda_runtime.h>
#include <cuda_bf16.h>
#include <math.h>
#include <stdint.h>

#define Bc 4
#define Tc 2048
#define Ec 1024
#define Hc 16
#define Dc 64
#define Fc 32
#define Mc (Bc*Tc)   // 8192

// ---------------- scratch (__device__ globals; allocation-free) -------------
__device__ float g_Q[Bc*Hc*Tc*Dc];   // (B,H,T,D) fp32 pre-rotary
__device__ float g_K[Bc*Hc*Tc*Dc];
__device__ float g_V[Bc*Hc*Tc*Dc];
__device__ float g_O[Bc*Tc*Ec];      // (B,T,E) attention output

// bf16 hi/lo splits
__device__ __align__(16) __nv_bfloat16 g_Ahi[Mc*Ec];
__device__ __align__(16) __nv_bfloat16 g_Alo[Mc*Ec];
__device__ __align__(16) __nv_bfloat16 g_Wh [3*Ec*Ec];
__device__ __align__(16) __nv_bfloat16 g_Wl [3*Ec*Ec];
__device__ __align__(16) __nv_bfloat16 g_WoH[Ec*Ec];
__device__ __align__(16) __nv_bfloat16 g_WoL[Ec*Ec];
__device__ __align__(16) __nv_bfloat16 g_Ohi[Mc*Ec];
__device__ __align__(16) __nv_bfloat16 g_Olo[Mc*Ec];
// post-rotary bf16 hi/lo Q and K
__device__ __align__(16) __nv_bfloat16 g_Qh[Bc*Hc*Tc*Dc];
__device__ __align__(16) __nv_bfloat16 g_Ql[Bc*Hc*Tc*Dc];
__device__ __align__(16) __nv_bfloat16 g_Kh[Bc*Hc*Tc*Dc];
__device__ __align__(16) __nv_bfloat16 g_Kl[Bc*Hc*Tc*Dc];

// mma.sync m16n8k16 bf16 (sm_80+ baseline PTX — compiles under compute_103)
__device__ __forceinline__ void mma_bf16(float* c, const uint32_t* a, const uint32_t* b) {
    asm volatile(
        "mma.sync.aligned.m16n8k16.row.col.f32.bf16.bf16.f32 "
        "{%0,%1,%2,%3}, {%4,%5,%6,%7}, {%8,%9}, {%0,%1,%2,%3};"
        : "+f"(c[0]), "+f"(c[1]), "+f"(c[2]), "+f"(c[3])
        : "r"(a[0]), "r"(a[1]), "r"(a[2]), "r"(a[3]), "r"(b[0]), "r"(b[1]));
}

// ---------------------------------------------------------------------------
// split: fp32 -> (hi, lo) bf16
// ---------------------------------------------------------------------------
template<int WHICH>
__global__ __launch_bounds__(256) void split_kernel(const float* __restrict__ src, int n)
{
    __nv_bfloat16* hi; __nv_bfloat16* lo;
    if (WHICH == 0) { hi = g_Ahi; lo = g_Alo; }
    else if (WHICH == 1) { hi = g_Wh; lo = g_Wl; }
    else if (WHICH == 2) { hi = g_WoH; lo = g_WoL; }
    else { hi = g_Ohi; lo = g_Olo; src = g_O; }

    for (int i = blockIdx.x * 256 + threadIdx.x; i < n; i += gridDim.x * 256) {
        float x = src[i];
        __nv_bfloat16 h = __float2bfloat16(x);
        hi[i] = h;
        lo[i] = __float2bfloat16(x - __bfloat162float(h));
    }
}

// ---------------------------------------------------------------------------
// mma.sync 3xBF16 GEMM: C[M,N] = A[M,1024] @ W[N,1024]^T + bias
// Block 256 thr = 8 warps (2M x 4N). Block tile 128x128, warp tile 64x32.
// K-chunk 32. Smem rows padded to 40 bf16 (conflict-free fragment loads).
// Fragments load as plain 4B LDS from K-major tiles (row.col mma).
// MODE 1: A=query splits, W=wqkv splits, scatter g_Q/g_K/g_V.  MODE 0: out-proj.
// ---------------------------------------------------------------------------
template<int MODE>
__global__ __launch_bounds__(256) void gemm_mma(
    const float* __restrict__ bias, float* __restrict__ C)
{
    __shared__ __nv_bfloat16 sAh[128*40], sAl[128*40], sBh[128*40], sBl[128*40];

    const int tid = threadIdx.x;
    const int wid = tid >> 5, lane = tid & 31;
    const int wm = wid >> 2, wn = wid & 3;
    const int r4 = lane >> 2, c2 = (lane & 3) * 2;

    const __nv_bfloat16 *Ah, *Al, *Bh, *Bl;
    if (MODE == 1) { Ah = g_Ahi; Al = g_Alo; Bh = g_Wh;  Bl = g_Wl;  }
    else           { Ah = g_Ohi; Al = g_Olo; Bh = g_WoH; Bl = g_WoL; }

    const int bm = blockIdx.y * 128;
    const int bn = blockIdx.x * 128;

    float acc[4][4][4];
    #pragma unroll
    for (int mf = 0; mf < 4; mf++)
        #pragma unroll
        for (int nf = 0; nf < 4; nf++)
            #pragma unroll
            for (int i = 0; i < 4; i++) acc[mf][nf][i] = 0.f;

    for (int kc = 0; kc < 32; kc++) {
        __syncthreads();
        #pragma unroll
        for (int i = 0; i < 4; i++) {
            int idx = i * 256 + tid;              // 0..1023
            int row = idx >> 3, sg = idx & 7;     // 8 x uint2 per 32-wide row
            size_t ga = (size_t)(bm + row) * 1024 + kc * 32 + sg * 4;
            *(uint2*)&sAh[row*40 + sg*4] = *(const uint2*)(Ah + ga);
            *(uint2*)&sAl[row*40 + sg*4] = *(const uint2*)(Al + ga);
            size_t gb = (size_t)(bn + row) * 1024 + kc * 32 + sg * 4;
            *(uint2*)&sBh[row*40 + sg*4] = *(const uint2*)(Bh + gb);
            *(uint2*)&sBl[row*40 + sg*4] = *(const uint2*)(Bl + gb);
        }
        __syncthreads();

        #pragma unroll
        for (int ks = 0; ks < 2; ks++) {
            const int k0 = ks * 16;
            uint32_t ah[4][4], al_[4][4], bh[4][2], bl_[4][2];
            #pragma unroll
            for (int mf = 0; mf < 4; mf++) {
                int r = wm*64 + mf*16 + r4;
                ah[mf][0]  = *(const uint32_t*)&sAh[ r     *40 + k0 + c2];
                ah[mf][1]  = *(const uint32_t*)&sAh[(r+8)  *40 + k0 + c2];
                ah[mf][2]  = *(const uint32_t*)&sAh[ r     *40 + k0 + 8 + c2];
                ah[mf][3]  = *(const uint32_t*)&sAh[(r+8)  *40 + k0 + 8 + c2];
                al_[mf][0] = *(const uint32_t*)&sAl[ r     *40 + k0 + c2];
                al_[mf][1] = *(const uint32_t*)&sAl[(r+8)  *40 + k0 + c2];
                al_[mf][2] = *(const uint32_t*)&sAl[ r     *40 + k0 + 8 + c2];
                al_[mf][3] = *(const uint32_t*)&sAl[(r+8)  *40 + k0 + 8 + c2];
            }
            #pragma unroll
            for (int nf = 0; nf < 4; nf++) {
                int n = wn*32 + nf*8 + r4;
                bh[nf][0]  = *(const uint32_t*)&sBh[n*40 + k0 + c2];
                bh[nf][1]  = *(const uint32_t*)&sBh[n*40 + k0 + 8 + c2];
                bl_[nf][0] = *(const uint32_t*)&sBl[n*40 + k0 + c2];
                bl_[nf][1] = *(const uint32_t*)&sBl[n*40 + k0 + 8 + c2];
            }
            #pragma unroll
            for (int mf = 0; mf < 4; mf++)
                #pragma unroll
                for (int nf = 0; nf < 4; nf++) {
                    mma_bf16(acc[mf][nf], ah[mf],  bh[nf]);
                    mma_bf16(acc[mf][nf], ah[mf],  bl_[nf]);
                    mma_bf16(acc[mf][nf], al_[mf], bh[nf]);
                }
        }
    }

    // epilogue: c0,c1 -> (m, n0..n0+1); c2,c3 -> (m+8, n0..n0+1)
    #pragma unroll
    for (int mf = 0; mf < 4; mf++) {
        int m0 = bm + wm*64 + mf*16 + r4;
        #pragma unroll
        for (int nf = 0; nf < 4; nf++) {
            int n0 = bn + wn*32 + nf*8 + c2;
            float bx = bias[n0], by = bias[n0 + 1];
            float2 v0 = make_float2(acc[mf][nf][0] + bx, acc[mf][nf][1] + by);
            float2 v1 = make_float2(acc[mf][nf][2] + bx, acc[mf][nf][3] + by);
            if (MODE == 0) {
                *(float2*)&C[(size_t)m0 * 1024 + n0] = v0;
                *(float2*)&C[(size_t)(m0+8) * 1024 + n0] = v1;
            } else {
                int which = n0 >> 10, nn = n0 & 1023;
                int hh = nn >> 6, dd = nn & 63;
                float* base = (which == 0) ? g_Q : (which == 1) ? g_K : g_V;
                int bb0 = m0 >> 11, tt0 = m0 & 2047;
                *(float2*)&base[((size_t)(bb0*Hc + hh)*Tc + tt0)*Dc + dd] = v0;
                int m1 = m0 + 8;
                int bb1 = m1 >> 11, tt1 = m1 & 2047;
                *(float2*)&base[((size_t)(bb1*Hc + hh)*Tc + tt1)*Dc + dd] = v1;
            }
        }
    }
}

// ---------------------------------------------------------------------------
// Rotary: one warp per (b,h,t), lane = pair f; writes bf16 hi/lo Q,K.
// ---------------------------------------------------------------------------
__global__ __launch_bounds__(256) void rotary_kernel(
    const float* __restrict__ pos, const float* __restrict__ freqs)
{
    int w = blockIdx.x * 8 + (threadIdx.x >> 5);
    int f = threadIdx.x & 31;
    int b = w / (Hc * Tc);
    int rem = w - b * (Hc * Tc);
    int h = rem / Tc;
    int t = rem - h * Tc;

    float px = pos[(size_t)(b * Tc + t) * 3 + 0];
    float py = pos[(size_t)(b * Tc + t) * 3 + 1];
    float pz = pos[(size_t)(b * Tc + t) * 3 + 2];
    float fx = freqs[(size_t)(h * Fc + f) * 3 + 0];
    float fy = freqs[(size_t)(h * Fc + f) * 3 + 1];
    float fz = freqs[(size_t)(h * Fc + f) * 3 + 2];
    float ang = px * fx + py * fy + pz * fz;
    float s, c;
    __sincosf(ang, &s, &c);

    size_t base = ((size_t)(b * Hc + h) * Tc + t) * Dc + 2 * f;

    float q0 = g_Q[base], q1 = g_Q[base + 1];
    float qr0 = q0 * c - q1 * s, qr1 = q0 * s + q1 * c;
    __nv_bfloat16 qh0 = __float2bfloat16(qr0), qh1 = __float2bfloat16(qr1);
    *(__nv_bfloat162*)(g_Qh + base) = __halves2bfloat162(qh0, qh1);
    *(__nv_bfloat162*)(g_Ql + base) = __halves2bfloat162(
        __float2bfloat16(qr0 - __bfloat162float(qh0)),
        __float2bfloat16(qr1 - __bfloat162float(qh1)));

    float k0 = g_K[base], k1 = g_K[base + 1];
    float kr0 = k0 * c - k1 * s, kr1 = k0 * s + k1 * c;
    __nv_bfloat16 kh0 = __float2bfloat16(kr0), kh1 = __float2bfloat16(kr1);
    *(__nv_bfloat162*)(g_Kh + base) = __halves2bfloat162(kh0, kh1);
    *(__nv_bfloat162*)(g_Kl + base) = __halves2bfloat162(
        __float2bfloat16(kr0 - __bfloat162float(kh0)),
        __float2bfloat16(kr1 - __bfloat162float(kh1)));
}

// ---------------------------------------------------------------------------
// Hybrid flash attention: S = Q.K^T via mma.sync (3xBF16), S through smem,
// per-thread-row online softmax (base-2), P.V in SIMT fp32 (R4-validated).
// Block 128 thr (4 warps), 128 q-rows; 64 key-tiles of 32. Warp w owns rows
// [32w,32w+32) — S roundtrip is warp-local (syncwarp suffices).
// ---------------------------------------------------------------------------
#define AQH 0
#define AQL 18432
#define AKH 36864
#define AKL 41472
#define AV  46080
#define AS  54272
#define ATT_SMEM 71168

__global__ __launch_bounds__(128) void attn_mma_kernel()
{
    extern __shared__ char smc[];
    __nv_bfloat16* sQh = (__nv_bfloat16*)(smc + AQH);   // [128][72]
    __nv_bfloat16* sQl = (__nv_bfloat16*)(smc + AQL);
    __nv_bfloat16* sKh = (__nv_bfloat16*)(smc + AKH);   // [32][72]
    __nv_bfloat16* sKl = (__nv_bfloat16*)(smc + AKL);
    float* sV = (float*)(smc + AV);                     // [32][64]
    float* sS = (float*)(smc + AS);                     // [128][33]

    const int tid = threadIdx.x, wid = tid >> 5, lane = tid & 31;
    const int r4 = lane >> 2, c2 = (lane & 3) * 2;
    const int qt = blockIdx.x, h = blockIdx.y, b = blockIdx.z;
    const size_t ho = (size_t)(b * Hc + h) * Tc * Dc;
    const int q0 = qt * 128;

    // Q tile (hi/lo) -> smem, once
    #pragma unroll
    for (int i = 0; i < 16; i++) {
        int idx = i * 128 + tid;
        int row = idx >> 4, sg = idx & 15;
        size_t g = ho + (size_t)(q0 + row) * Dc + sg * 4;
        *(uint2*)&sQh[row*72 + sg*4] = *(const uint2*)(g_Qh + g);
        *(uint2*)&sQl[row*72 + sg*4] = *(const uint2*)(g_Ql + g);
    }

    float o[64];
    #pragma unroll
    for (int d = 0; d < 64; d++) o[d] = 0.f;
    float mval = -1e30f, l = 0.f;
    const float qs = 0.125f * 1.4426950408889634f;   // 1/sqrt(D) * log2(e)

    for (int kt = 0; kt < 64; kt++) {
        __syncthreads();   // prior tile's K/V reads complete (also orders Q load at kt=0)
        #pragma unroll
        for (int i = 0; i < 4; i++) {
            int idx = i * 128 + tid;
            int row = idx >> 4, sg = idx & 15;
            size_t g = ho + (size_t)(kt * 32 + row) * Dc + sg * 4;
            *(uint2*)&sKh[row*72 + sg*4] = *(const uint2*)(g_Kh + g);
            *(uint2*)&sKl[row*72 + sg*4] = *(const uint2*)(g_Kl + g);
            *(float4*)&sV[row*64 + sg*4] = *(const float4*)(g_V + g);
        }
        __syncthreads();

        // S = Q.K^T for this warp's 32 rows x 32 keys (3 products)
        float acc[2][4][4];
        #pragma unroll
        for (int mf = 0; mf < 2; mf++)
            #pragma unroll
            for (int nf = 0; nf < 4; nf++)
                #pragma unroll
                for (int i = 0; i < 4; i++) acc[mf][nf][i] = 0.f;

        #pragma unroll
        for (int ks = 0; ks < 4; ks++) {
            const int k0 = ks * 16;
            uint32_t ah[2][4], al_[2][4], bh[4][2], bl_[4][2];
            #pragma unroll
            for (int mf = 0; mf < 2; mf++) {
                int r = wid*32 + mf*16 + r4;
                ah[mf][0]  = *(const uint32_t*)&sQh[ r    *72 + k0 + c2];
                ah[mf][1]  = *(const uint32_t*)&sQh[(r+8) *72 + k0 + c2];
                ah[mf][2]  = *(const uint32_t*)&sQh[ r    *72 + k0 + 8 + c2];
                ah[mf][3]  = *(const uint32_t*)&sQh[(r+8) *72 + k0 + 8 + c2];
                al_[mf][0] = *(const uint32_t*)&sQl[ r    *72 + k0 + c2];
                al_[mf][1] = *(const uint32_t*)&sQl[(r+8) *72 + k0 + c2];
                al_[mf][2] = *(const uint32_t*)&sQl[ r    *72 + k0 + 8 + c2];
                al_[mf][3] = *(const uint32_t*)&sQl[(r+8) *72 + k0 + 8 + c2];
            }
            #pragma unroll
            for (int nf = 0; nf < 4; nf++) {
                int n = nf*8 + r4;
                bh[nf][0]  = *(const uint32_t*)&sKh[n*72 + k0 + c2];
                bh[nf][1]  = *(const uint32_t*)&sKh[n*72 + k0 + 8 + c2];
                bl_[nf][0] = *(const uint32_t*)&sKl[n*72 + k0 + c2];
                bl_[nf][1] = *(const uint32_t*)&sKl[n*72 + k0 + 8 + c2];
            }
            #pragma unroll
            for (int mf = 0; mf < 2; mf++)
                #pragma unroll
                for (int nf = 0; nf < 4; nf++) {
                    mma_bf16(acc[mf][nf], ah[mf],  bh[nf]);
                    mma_bf16(acc[mf][nf], ah[mf],  bl_[nf]);
                    mma_bf16(acc[mf][nf], al_[mf], bh[nf]);
                }
        }

        // fragments -> sS (warp-local rows)
        #pragma unroll
        for (int mf = 0; mf < 2; mf++) {
            int r = wid*32 + mf*16 + r4;
            #pragma unroll
            for (int nf = 0; nf < 4; nf++) {
                int cc = nf*8 + c2;
                sS[ r    *33 + cc    ] = acc[mf][nf][0];
                sS[ r    *33 + cc + 1] = acc[mf][nf][1];
                sS[(r+8) *33 + cc    ] = acc[mf][nf][2];
                sS[(r+8) *33 + cc + 1] = acc[mf][nf][3];
            }
        }
        __syncwarp();

        // per-thread row softmax (row = tid) + SIMT fp32 PV
        float s[32];
        #pragma unroll
        for (int j = 0; j < 32; j++) s[j] = sS[tid*33 + j] * qs;

        float tm = mval;
        #pragma unroll
        for (int j = 0; j < 32; j++) tm = fmaxf(tm, s[j]);
        float corr = exp2f(mval - tm);
        mval = tm;
        l *= corr;
        #pragma unroll
        for (int d = 0; d < 64; d++) o[d] *= corr;

        for (int j = 0; j < 32; j++) {
            float p = exp2f(s[j] - mval);
            l += p;
            const float4* vr = (const float4*)(sV + j * 64);
            #pragma unroll
            for (int k4 = 0; k4 < 16; k4++) {
                float4 vv = vr[k4];
                o[4*k4+0] += p * vv.x; o[4*k4+1] += p * vv.y;
                o[4*k4+2] += p * vv.z; o[4*k4+3] += p * vv.w;
            }
        }
    }

    float inv = 1.f / l;
    float* od = g_O + (size_t)(b * Tc + q0 + tid) * Ec + h * Dc;
    #pragma unroll
    for (int k4 = 0; k4 < 16; k4++) {
        float4 v;
        v.x = o[4*k4+0] * inv; v.y = o[4*k4+1] * inv;
        v.z = o[4*k4+2] * inv; v.w = o[4*k4+3] * inv;
        ((float4*)od)[k4] = v;
    }
}

// ---------------------------------------------------------------------------
extern "C" void kernel_launch(void* const* d_in, const int* in_sizes, int n_in,
                              void* d_out, int out_size)
{
    const float* query = (const float*)d_in[0];   // (B,T,E)
    const float* pos   = (const float*)d_in[1];   // (B,T,3)
    const float* wqkv  = (const float*)d_in[2];   // (3E,E)
    const float* bqkv  = (const float*)d_in[3];   // (3E,)
    const float* wo    = (const float*)d_in[4];   // (E,E)
    const float* bo    = (const float*)d_in[5];   // (E,)
    const float* freqs = (const float*)d_in[6];   // (H,F,3)
    float* out = (float*)d_out;

    cudaFuncSetAttribute(attn_mma_kernel, cudaFuncAttributeMaxDynamicSharedMemorySize, ATT_SMEM);

    // 0) hi/lo bf16 splits of activations + weights
    split_kernel<0><<<4096, 256>>>(query, Mc * Ec);
    split_kernel<1><<<2048, 256>>>(wqkv, 3 * Ec * Ec);
    split_kernel<2><<<1024, 256>>>(wo, Ec * Ec);

    // 1) QKV projection (mma.sync 3xBF16), scattered to (B,H,T,D)
    {
        dim3 grid(3 * Ec / 128, Mc / 128);       // (24, 64)
        gemm_mma<1><<<grid, 256>>>(bqkv, nullptr);
    }
    // 2) rotary on Q and K -> bf16 hi/lo
    rotary_kernel<<<Bc * Hc * Tc / 8, 256>>>(pos, freqs);

    // 3) hybrid attention (QK on tensor cores via mma.sync, PV SIMT fp32)
    {
        dim3 grid(Tc / 128, Hc, Bc);             // (16, 16, 4)
        attn_mma_kernel<<<grid, 128, ATT_SMEM>>>();
    }
    // 4) split attention output, then out-projection (mma.sync 3xBF16)
    split_kernel<3><<<4096, 256>>>(nullptr, Mc * Ec);
    {
        dim3 grid(Ec / 128, Mc / 128);           // (8, 64)
        gemm_mma<0><<<grid, 256>>>(bo, out);
    }
}